// round 15
// baseline (speedup 1.0000x reference)
#include <cuda_runtime.h>
#include <cuda_fp16.h>
#include <math.h>
#include <stdint.h>

#define BATCH   8
#define SEQ     2048
#define NTOK    16384
#define FDIM    128
#define DMODEL  512
#define DINNER  1024
#define NLAYERS 4
#define VOCAB   256
#define NHEADS  384

// ---------------- scratch (device globals; no allocs) ----------------
__device__ float  g_x [NTOK * DMODEL];                        // residual (fp32)
__device__ __half g_n [NTOK * DMODEL];                        // LN out
__device__ __half g_h [NTOK * DINNER];                        // GLU out
__device__ __half g_fr[NTOK * FDIM];                          // frames
__device__ __half g_bt_inproj[DMODEL * FDIM];
__device__ __half g_bt_win   [NLAYERS * 2 * DINNER * DMODEL];
__device__ __half g_bt_wout  [NLAYERS * DMODEL * DINNER];
__device__ __half g_wh_t     [NHEADS * DMODEL];
__device__ float  g_bh       [NHEADS];

// ---------------- helpers ----------------
__device__ __forceinline__ uint32_t smem_u32(const void* p) {
    uint32_t a;
    asm("{ .reg .u64 t; cvta.to.shared.u64 t, %1; cvt.u32.u64 %0, t; }" : "=r"(a) : "l"(p));
    return a;
}
__device__ __forceinline__ void mma16(float* d, const uint32_t* a, uint32_t b0, uint32_t b1) {
    asm volatile("mma.sync.aligned.m16n8k16.row.col.f32.f16.f16.f32 "
                 "{%0,%1,%2,%3}, {%4,%5,%6,%7}, {%8,%9}, {%0,%1,%2,%3};"
                 : "+f"(d[0]), "+f"(d[1]), "+f"(d[2]), "+f"(d[3])
                 : "r"(a[0]), "r"(a[1]), "r"(a[2]), "r"(a[3]), "r"(b0), "r"(b1));
}
__device__ __forceinline__ void mma16h(uint32_t* d, const uint32_t* a, uint32_t b0, uint32_t b1) {
    asm volatile("mma.sync.aligned.m16n8k16.row.col.f16.f16.f16.f16 "
                 "{%0,%1}, {%2,%3,%4,%5}, {%6,%7}, {%0,%1};"
                 : "+r"(d[0]), "+r"(d[1])
                 : "r"(a[0]), "r"(a[1]), "r"(a[2]), "r"(a[3]), "r"(b0), "r"(b1));
}
__device__ __forceinline__ void ldsm4(uint32_t& r0, uint32_t& r1, uint32_t& r2, uint32_t& r3,
                                      uint32_t addr) {
    asm volatile("ldmatrix.sync.aligned.m8n8.x4.shared.b16 {%0,%1,%2,%3}, [%4];"
                 : "=r"(r0), "=r"(r1), "=r"(r2), "=r"(r3) : "r"(addr));
}
__device__ __forceinline__ void cpa16(uint32_t s, const void* g) {
    asm volatile("cp.async.cg.shared.global [%0], [%1], 16;" :: "r"(s), "l"(g));
}
#define CP_COMMIT() asm volatile("cp.async.commit_group;")
#define CP_WAIT1()  asm volatile("cp.async.wait_group 1;")
#define CP_WAIT0()  asm volatile("cp.async.wait_group 0;")

#define CHK   64
#define LDKH  72
#define LDKB  144
#define TILE_B (128 * LDKB)
#define STAGE_B (2 * TILE_B)
#define NSTAGE 3
#define SMEM_BYTES (NSTAGE * STAGE_B)  // 110592

// ---- fp16 mma.sync GEMM: 256 thr, 64x32 warp tile ----
// MODE 1: C = acc + bias + pos_emb[s,col]          (fp32 accum)
// MODE 2: C = (aux + acc + bias) * decay(s)        (fp32 accum)
// MODE 3: heads: mask ? acc+bias : 0               (fp32 accum)
// MODE 4: GLU fused, h = u*silu(g); fp16 sub-accum drained to fp32 every 16 K
template<int MODE, int KT>
__global__ __launch_bounds__(256, 2)
void gemm_mma(const __half* __restrict__ A, const __half* __restrict__ Bt,
              const float* __restrict__ bias, float* __restrict__ C,
              int Nfull,
              const float* __restrict__ aux, const int* __restrict__ mask,
              float* __restrict__ out2)
{
    extern __shared__ uint32_t smem[];
    const int tid  = threadIdx.x;
    const int wid  = tid >> 5, lane = tid & 31;
    const int r    = lane >> 2, c = lane & 3;
    const int wm   = (wid & 1) * 64;
    const int wn   = (wid >> 1) * 32;
    const int r0   = blockIdx.y * 128;
    const int c0   = blockIdx.x * ((MODE == 4) ? 64 : 128);

    const int srw = tid >> 3;
    const int seg = (tid & 7) * 16;

    auto browf = [&](int t) -> int {
        if (MODE == 4) {
            const int wq = t >> 5, i5 = t & 31;
            return c0 + wq * 16 + (i5 & 15) + ((i5 >> 4) ? DINNER : 0);
        }
        return c0 + t;
    };

    const uint32_t sbase = smem_u32(smem);
    constexpr int nch = KT / CHK;

    auto stage = [&](int ch) {
        const int buf = ch % NSTAGE;
        const int kc = ch * CHK;
        const uint32_t aB = sbase + buf * STAGE_B;
        const uint32_t bB = aB + TILE_B;
        #pragma unroll
        for (int i = 0; i < 4; i++) {
            const int rw = srw + 32 * i;
            cpa16(aB + rw * LDKB + seg,
                  A + (size_t)(r0 + rw) * KT + kc + seg / 2);
        }
        #pragma unroll
        for (int i = 0; i < 4; i++) {
            const int rw = srw + 32 * i;
            cpa16(bB + rw * LDKB + seg,
                  Bt + (size_t)browf(rw) * KT + kc + seg / 2);
        }
        CP_COMMIT();
    };

    const int aRow = (lane & 7) + ((lane >> 3) & 1) * 8;
    const int aKh  = lane >> 4;
    uint32_t aOff[4];
    #pragma unroll
    for (int mt = 0; mt < 4; mt++)
        aOff[mt] = (wm + mt * 16 + aRow) * LDKB + aKh * 16;
    const int bN = wn + (lane >> 3) * 8 + (lane & 7);
    const uint32_t bOff0 = bN * LDKB;
    const uint32_t bOff1 = bN * LDKB + 16;

    float acc[4][4][4];
    #pragma unroll
    for (int mt = 0; mt < 4; mt++)
        #pragma unroll
        for (int nt = 0; nt < 4; nt++)
            #pragma unroll
            for (int q = 0; q < 4; q++) acc[mt][nt][q] = 0.f;

    uint32_t hacc[4][4][2];     // MODE4 only: fp16 sub-accumulators (one k-step live range)
    if (MODE == 4) {
        #pragma unroll
        for (int mt = 0; mt < 4; mt++)
            #pragma unroll
            for (int nt = 0; nt < 4; nt++) { hacc[mt][nt][0] = 0u; hacc[mt][nt][1] = 0u; }
    }

    stage(0);
    if (nch > 1) stage(1);

    #pragma unroll
    for (int ch = 0; ch < nch; ch++) {
        if (ch + 1 < nch) { CP_WAIT1(); } else { CP_WAIT0(); }
        __syncthreads();
        if (ch + 2 < nch) stage(ch + 2);

        const uint32_t sA = sbase + (ch % NSTAGE) * STAGE_B;
        const uint32_t sB = sA + TILE_B;
        #pragma unroll
        for (int ks = 0; ks < 4; ks++) {
            const uint32_t kbB = ks * 32;
            uint32_t b0[4], b1[4];
            ldsm4(b0[0], b0[1], b0[2], b0[3], sB + bOff0 + kbB);
            ldsm4(b1[0], b1[1], b1[2], b1[3], sB + bOff1 + kbB);
            #pragma unroll
            for (int mt = 0; mt < 4; mt++) {
                uint32_t af[4];
                ldsm4(af[0], af[1], af[2], af[3], sA + aOff[mt] + kbB);
                #pragma unroll
                for (int nt = 0; nt < 4; nt++) {
                    if (MODE == 4) mma16h(hacc[mt][nt], af, b0[nt], b1[nt]);
                    else           mma16(acc[mt][nt], af, b0[nt], b1[nt]);
                }
            }
            if (MODE == 4) {   // drain fp16 sub-accumulators every 16 K
                #pragma unroll
                for (int mt = 0; mt < 4; mt++)
                    #pragma unroll
                    for (int nt = 0; nt < 4; nt++) {
                        float2 lo = __half22float2(*reinterpret_cast<__half2*>(&hacc[mt][nt][0]));
                        float2 hi = __half22float2(*reinterpret_cast<__half2*>(&hacc[mt][nt][1]));
                        acc[mt][nt][0] += lo.x;  acc[mt][nt][1] += lo.y;
                        acc[mt][nt][2] += hi.x;  acc[mt][nt][3] += hi.y;
                        hacc[mt][nt][0] = 0u;    hacc[mt][nt][1] = 0u;
                    }
            }
        }
    }

    // ---------------- epilogue ----------------
    if (MODE == 4) {
        __half* Ch = (__half*)C;
        const int wq = wid >> 1;
        #pragma unroll
        for (int mt = 0; mt < 4; mt++) {
            #pragma unroll
            for (int h = 0; h < 2; h++) {
                const int row = r0 + wm + mt * 16 + r + h * 8;
                #pragma unroll
                for (int nt = 0; nt < 2; nt++) {
                    const int ucol = c0 + wq * 16 + nt * 8 + 2 * c;
                    float2 bu = *(const float2*)(bias + ucol);
                    float2 bg = *(const float2*)(bias + DINNER + ucol);
                    float ux = acc[mt][nt][2*h+0] + bu.x;
                    float uy = acc[mt][nt][2*h+1] + bu.y;
                    float gx = acc[mt][nt+2][2*h+0] + bg.x;
                    float gy = acc[mt][nt+2][2*h+1] + bg.y;
                    float vx = ux * gx / (1.0f + __expf(-gx));
                    float vy = uy * gy / (1.0f + __expf(-gy));
                    *(__half2*)(Ch + (size_t)row * DINNER + ucol) =
                        __floats2half2_rn(vx, vy);
                }
            }
        }
        return;
    }

    #pragma unroll
    for (int mt = 0; mt < 4; mt++) {
        #pragma unroll
        for (int h = 0; h < 2; h++) {
            const int row = r0 + wm + mt * 16 + r + h * 8;
            const int s   = row & (SEQ - 1);
            float dec = 1.0f, mk = 1.0f;
            if (MODE == 2) dec = (((s + 1) % 10) == 0) ? 0.1f : 1.0f;
            if (MODE == 3) mk  = (mask[row] != 0) ? 1.0f : 0.0f;
            #pragma unroll
            for (int nt = 0; nt < 4; nt++) {
                const int col = c0 + wn + nt * 8 + 2 * c;
                float2 bv = *(const float2*)(bias + col);
                float2 v;
                v.x = acc[mt][nt][2*h+0] + bv.x;
                v.y = acc[mt][nt][2*h+1] + bv.y;
                if (MODE == 1) {
                    float2 p = *(const float2*)(aux + (size_t)s * DMODEL + col);
                    v.x += p.x; v.y += p.y;
                }
                if (MODE == 2) {
                    float2 xv = *(const float2*)(aux + (size_t)row * Nfull + col);
                    v.x = (v.x + xv.x) * dec;
                    v.y = (v.y + xv.y) * dec;
                }
                if (MODE == 3) {
                    v.x *= mk; v.y *= mk;
                    if (col < FDIM)
                        *(float2*)(C + (size_t)row * FDIM + col) = v;
                    else
                        *(float2*)(out2 + (size_t)row * VOCAB + (col - FDIM)) = v;
                } else {
                    *(float2*)(C + (size_t)row * Nfull + col) = v;
                }
            }
        }
    }
}

// ---------------- fused prep: all weight/input conversion in ONE launch ----------------
__device__ __forceinline__ void tile_transpose(
    float (*t)[33], const float* __restrict__ in, __half* __restrict__ out, int K, int N)
{
    const int n0 = blockIdx.x * 32, k0 = blockIdx.y * 32;
    const int x = threadIdx.x, y = threadIdx.y;
    #pragma unroll
    for (int i = 0; i < 32; i += 8)
        t[y + i][x] = in[(size_t)(k0 + y + i) * N + n0 + x];
    __syncthreads();
    #pragma unroll
    for (int i = 0; i < 32; i += 8)
        out[(size_t)(n0 + y + i) * K + k0 + x] = __float2half_rn(t[x][y + i]);
}

__global__ void prep_all(const float* __restrict__ W_in, const float* __restrict__ W_out,
                         const float* __restrict__ W_in_proj,
                         const float* __restrict__ Wf, const float* __restrict__ bf,
                         const float* __restrict__ Ws, const float* __restrict__ bs,
                         const float* __restrict__ frames,
                         __half* __restrict__ btI, __half* __restrict__ btO,
                         __half* __restrict__ btP,
                         __half* __restrict__ wht, float* __restrict__ bh,
                         __half* __restrict__ fr)
{
    __shared__ float t[32][33];
    const int z = blockIdx.z;
    if (z < 4) {
        if (blockIdx.y >= DMODEL / 32) return;
        tile_transpose(t, W_in + (size_t)z * DMODEL * 2 * DINNER,
                       btI + (size_t)z * 2 * DINNER * DMODEL, DMODEL, 2 * DINNER);
    } else if (z < 8) {
        if (blockIdx.x >= DMODEL / 32) return;
        tile_transpose(t, W_out + (size_t)(z - 4) * DINNER * DMODEL,
                       btO + (size_t)(z - 4) * DMODEL * DINNER, DINNER, DMODEL);
    } else if (z == 8) {
        if (blockIdx.x >= DMODEL / 32 || blockIdx.y >= FDIM / 32) return;
        tile_transpose(t, W_in_proj, btP, FDIM, DMODEL);
    } else {
        const int flat = (blockIdx.y * 64 + blockIdx.x) * 256 + threadIdx.y * 32 + threadIdx.x;
        {
            float4 v = ((const float4*)frames)[flat];
            __half2* o = (__half2*)fr + 2 * flat;
            o[0] = __floats2half2_rn(v.x, v.y);
            o[1] = __floats2half2_rn(v.z, v.w);
        }
        if (flat < DMODEL * NHEADS) {
            const int rr = flat / NHEADS, cc = flat % NHEADS;
            wht[(size_t)cc * DMODEL + rr] =
                __float2half_rn((cc < FDIM) ? Wf[rr * FDIM + cc] : Ws[rr * VOCAB + (cc - FDIM)]);
        }
        if (flat < NHEADS) bh[flat] = (flat < FDIM) ? bf[flat] : bs[flat - FDIM];
    }
}

// ---------------- LayerNorm: one warp per row; half output ----------------
__global__ __launch_bounds__(256)
void ln_kernel(const float* __restrict__ x, const float* __restrict__ sc,
               const float* __restrict__ bi, __half* __restrict__ out)
{
    const int row  = blockIdx.x * 8 + threadIdx.y;
    const int lane = threadIdx.x;
    const float4* xr = (const float4*)(x + (size_t)row * DMODEL);
    float4 v[4]; float s = 0.f;
    #pragma unroll
    for (int i = 0; i < 4; i++) { v[i] = xr[lane + 32*i]; s += v[i].x + v[i].y + v[i].z + v[i].w; }
    #pragma unroll
    for (int o = 16; o > 0; o >>= 1) s += __shfl_xor_sync(0xffffffffu, s, o);
    const float mu = s * (1.0f / DMODEL);
    float q = 0.f;
    #pragma unroll
    for (int i = 0; i < 4; i++) {
        float d;
        d = v[i].x - mu; q += d*d;  d = v[i].y - mu; q += d*d;
        d = v[i].z - mu; q += d*d;  d = v[i].w - mu; q += d*d;
    }
    #pragma unroll
    for (int o = 16; o > 0; o >>= 1) q += __shfl_xor_sync(0xffffffffu, q, o);
    const float inv = rsqrtf(q * (1.0f / DMODEL) + 1e-5f);
    const float4* s4 = (const float4*)sc;
    const float4* b4 = (const float4*)bi;
    __half2* o2 = (__half2*)(out + (size_t)row * DMODEL);
    #pragma unroll
    for (int i = 0; i < 4; i++) {
        const int cc = lane + 32*i;
        float4 sv = s4[cc], bv = b4[cc];
        float rx = (v[i].x - mu) * inv * sv.x + bv.x;
        float ry = (v[i].y - mu) * inv * sv.y + bv.y;
        float rz = (v[i].z - mu) * inv * sv.z + bv.z;
        float rw = (v[i].w - mu) * inv * sv.w + bv.w;
        o2[2*cc]   = __floats2half2_rn(rx, ry);
        o2[2*cc+1] = __floats2half2_rn(rz, rw);
    }
}

// -----------------------------------------------------------------------------
extern "C" void kernel_launch(void* const* d_in, const int* in_sizes, int n_in,
                              void* d_out, int out_size)
{
    const float* frames    = (const float*)d_in[0];
    const int*   mask      = (const int*)d_in[1];
    const float* W_in_proj = (const float*)d_in[2];
    const float* b_in_proj = (const float*)d_in[3];
    const float* pos_emb   = (const float*)d_in[4];
    const float* ln_scale  = (const float*)d_in[5];
    const float* ln_bias   = (const float*)d_in[6];
    const float* W_in      = (const float*)d_in[7];
    const float* b_in      = (const float*)d_in[8];
    const float* W_out     = (const float*)d_in[9];
    const float* b_out     = (const float*)d_in[10];
    const float* fn_scale  = (const float*)d_in[11];
    const float* fn_bias   = (const float*)d_in[12];
    const float* W_frame   = (const float*)d_in[13];
    const float* b_frame   = (const float*)d_in[14];
    const float* W_sym     = (const float*)d_in[15];
    const float* b_sym     = (const float*)d_in[16];

    float *px, *pbh;
    __half *pn, *ph, *pfr, *pbtP, *pbtI, *pbtO, *pwht;
    cudaGetSymbolAddress((void**)&px,   g_x);
    cudaGetSymbolAddress((void**)&pn,   g_n);
    cudaGetSymbolAddress((void**)&ph,   g_h);
    cudaGetSymbolAddress((void**)&pfr,  g_fr);
    cudaGetSymbolAddress((void**)&pbtP, g_bt_inproj);
    cudaGetSymbolAddress((void**)&pbtI, g_bt_win);
    cudaGetSymbolAddress((void**)&pbtO, g_bt_wout);
    cudaGetSymbolAddress((void**)&pwht, g_wh_t);
    cudaGetSymbolAddress((void**)&pbh,  g_bh);

    float* out_frame = (float*)d_out;
    float* out_sym   = (float*)d_out + (size_t)NTOK * FDIM;

    cudaFuncSetAttribute(gemm_mma<1,128>,  cudaFuncAttributeMaxDynamicSharedMemorySize, SMEM_BYTES);
    cudaFuncSetAttribute(gemm_mma<4,512>,  cudaFuncAttributeMaxDynamicSharedMemorySize, SMEM_BYTES);
    cudaFuncSetAttribute(gemm_mma<2,1024>, cudaFuncAttributeMaxDynamicSharedMemorySize, SMEM_BYTES);
    cudaFuncSetAttribute(gemm_mma<3,512>,  cudaFuncAttributeMaxDynamicSharedMemorySize, SMEM_BYTES);

    // ---- single fused prep launch ----
    {
        dim3 b(32, 8);
        dim3 g(64, 32, 10);
        prep_all<<<g, b>>>(W_in, W_out, W_in_proj, W_frame, b_frame, W_sym, b_sym,
                           frames, pbtI, pbtO, pbtP, pwht, pbh, pfr);
    }

    const dim3 lnb(32, 8);
    const int  lng = NTOK / 8;

    // 1) in_proj + pos_emb
    gemm_mma<1,128><<<dim3(DMODEL/128, NTOK/128), 256, SMEM_BYTES>>>(
        pfr, pbtP, b_in_proj, px, DMODEL, pos_emb, nullptr, nullptr);

    // 2) layers: LN -> fused GEMM+GLU -> GEMM+residual
    for (int l = 0; l < NLAYERS; l++) {
        ln_kernel<<<lng, lnb>>>(px, ln_scale + l*DMODEL, ln_bias + l*DMODEL, pn);

        gemm_mma<4,512><<<dim3(DINNER/64, NTOK/128), 256, SMEM_BYTES>>>(
            pn, pbtI + (size_t)l * 2*DINNER*DMODEL,
            b_in + (size_t)l * 2*DINNER, (float*)ph, DINNER,
            nullptr, nullptr, nullptr);

        gemm_mma<2,1024><<<dim3(DMODEL/128, NTOK/128), 256, SMEM_BYTES>>>(
            ph, pbtO + (size_t)l * DMODEL*DINNER,
            b_out + (size_t)l * DMODEL, px, DMODEL,
            px, nullptr, nullptr);
    }

    // 3) final LN
    ln_kernel<<<lng, lnb>>>(px, fn_scale, fn_bias, pn);

    // 4) heads
    gemm_mma<3,512><<<dim3(NHEADS/128, NTOK/128), 256, SMEM_BYTES>>>(
        pn, pwht, pbh, out_frame, NHEADS,
        nullptr, mask, out_sym);
}

// round 16
// speedup vs baseline: 1.2779x; 1.2779x over previous
#include <cuda_runtime.h>
#include <cuda_fp16.h>
#include <math.h>
#include <stdint.h>

#define BATCH   8
#define SEQ     2048
#define NTOK    16384
#define FDIM    128
#define DMODEL  512
#define DINNER  1024
#define NLAYERS 4
#define VOCAB   256
#define NHEADS  384

// ---------------- scratch (device globals; no allocs) ----------------
__device__ float  g_x [NTOK * DMODEL];                        // residual (fp32)
__device__ __half g_n [NTOK * DMODEL];                        // LN out
__device__ __half g_h [NTOK * DINNER];                        // GLU out
__device__ __half g_fr[NTOK * FDIM];                          // frames
__device__ __half g_bt_inproj[DMODEL * FDIM];
__device__ __half g_bt_win   [NLAYERS * 2 * DINNER * DMODEL];
__device__ __half g_bt_wout  [NLAYERS * DMODEL * DINNER];
__device__ __half g_wh_t     [NHEADS * DMODEL];
__device__ float  g_bh       [NHEADS];

// ---------------- helpers ----------------
__device__ __forceinline__ uint32_t smem_u32(const void* p) {
    uint32_t a;
    asm("{ .reg .u64 t; cvta.to.shared.u64 t, %1; cvt.u32.u64 %0, t; }" : "=r"(a) : "l"(p));
    return a;
}
__device__ __forceinline__ void mma16(float* d, const uint32_t* a, uint32_t b0, uint32_t b1) {
    asm volatile("mma.sync.aligned.m16n8k16.row.col.f32.f16.f16.f32 "
                 "{%0,%1,%2,%3}, {%4,%5,%6,%7}, {%8,%9}, {%0,%1,%2,%3};"
                 : "+f"(d[0]), "+f"(d[1]), "+f"(d[2]), "+f"(d[3])
                 : "r"(a[0]), "r"(a[1]), "r"(a[2]), "r"(a[3]), "r"(b0), "r"(b1));
}
__device__ __forceinline__ void ldsm4(uint32_t& r0, uint32_t& r1, uint32_t& r2, uint32_t& r3,
                                      uint32_t addr) {
    asm volatile("ldmatrix.sync.aligned.m8n8.x4.shared.b16 {%0,%1,%2,%3}, [%4];"
                 : "=r"(r0), "=r"(r1), "=r"(r2), "=r"(r3) : "r"(addr));
}
__device__ __forceinline__ void cpa16(uint32_t s, const void* g) {
    asm volatile("cp.async.cg.shared.global [%0], [%1], 16;" :: "r"(s), "l"(g));
}
#define CP_COMMIT() asm volatile("cp.async.commit_group;")
#define CP_WAIT1()  asm volatile("cp.async.wait_group 1;")
#define CP_WAIT0()  asm volatile("cp.async.wait_group 0;")

#define CHK   64
#define LDKH  72
#define LDKB  144
#define TILE_B (128 * LDKB)
#define STAGE_B (2 * TILE_B)
#define NSTAGE 3
#define SMEM_BYTES (NSTAGE * STAGE_B)  // 110592

// ---- fp16 mma.sync GEMM (fp32 accum): 256 thr, 64x32 warp tile, 3-buf 1-sync ----
// MODE 1: C = acc + bias + pos_emb[s,col]          (fp32 out)
// MODE 2: C = (aux + acc + bias) * decay(s)        (fp32 out, in-place residual)
// MODE 3: heads: mask ? acc+bias : 0; split frame/sym (fp32 out)
// MODE 4: GLU fused: h = u*silu(g), stored half (C recast)
template<int MODE, int KT>
__global__ __launch_bounds__(256, 2)
void gemm_mma(const __half* __restrict__ A, const __half* __restrict__ Bt,
              const float* __restrict__ bias, float* __restrict__ C,
              int Nfull,
              const float* __restrict__ aux, const int* __restrict__ mask,
              float* __restrict__ out2)
{
    extern __shared__ uint32_t smem[];
    const int tid  = threadIdx.x;
    const int wid  = tid >> 5, lane = tid & 31;
    const int r    = lane >> 2, c = lane & 3;
    const int wm   = (wid & 1) * 64;
    const int wn   = (wid >> 1) * 32;
    const int r0   = blockIdx.y * 128;
    const int c0   = blockIdx.x * ((MODE == 4) ? 64 : 128);

    const int srw = tid >> 3;
    const int seg = (tid & 7) * 16;

    auto browf = [&](int t) -> int {
        if (MODE == 4) {
            const int wq = t >> 5, i5 = t & 31;
            return c0 + wq * 16 + (i5 & 15) + ((i5 >> 4) ? DINNER : 0);
        }
        return c0 + t;
    };

    const uint32_t sbase = smem_u32(smem);
    constexpr int nch = KT / CHK;

    auto stage = [&](int ch) {
        const int buf = ch % NSTAGE;
        const int kc = ch * CHK;
        const uint32_t aB = sbase + buf * STAGE_B;
        const uint32_t bB = aB + TILE_B;
        #pragma unroll
        for (int i = 0; i < 4; i++) {
            const int rw = srw + 32 * i;
            cpa16(aB + rw * LDKB + seg,
                  A + (size_t)(r0 + rw) * KT + kc + seg / 2);
        }
        #pragma unroll
        for (int i = 0; i < 4; i++) {
            const int rw = srw + 32 * i;
            cpa16(bB + rw * LDKB + seg,
                  Bt + (size_t)browf(rw) * KT + kc + seg / 2);
        }
        CP_COMMIT();
    };

    const int aRow = (lane & 7) + ((lane >> 3) & 1) * 8;
    const int aKh  = lane >> 4;
    uint32_t aOff[4];
    #pragma unroll
    for (int mt = 0; mt < 4; mt++)
        aOff[mt] = (wm + mt * 16 + aRow) * LDKB + aKh * 16;
    const int bN = wn + (lane >> 3) * 8 + (lane & 7);
    const uint32_t bOff0 = bN * LDKB;
    const uint32_t bOff1 = bN * LDKB + 16;

    float acc[4][4][4];
    #pragma unroll
    for (int mt = 0; mt < 4; mt++)
        #pragma unroll
        for (int nt = 0; nt < 4; nt++)
            #pragma unroll
            for (int q = 0; q < 4; q++) acc[mt][nt][q] = 0.f;

    stage(0);
    if (nch > 1) stage(1);

    #pragma unroll
    for (int ch = 0; ch < nch; ch++) {
        if (ch + 1 < nch) { CP_WAIT1(); } else { CP_WAIT0(); }
        __syncthreads();
        // safe: buffer (ch+2)%3 == (ch-1)%3; all warps finished compute(ch-1)
        if (ch + 2 < nch) stage(ch + 2);

        const uint32_t sA = sbase + (ch % NSTAGE) * STAGE_B;
        const uint32_t sB = sA + TILE_B;
        #pragma unroll
        for (int ks = 0; ks < 4; ks++) {
            const uint32_t kbB = ks * 32;
            uint32_t b0[4], b1[4];
            ldsm4(b0[0], b0[1], b0[2], b0[3], sB + bOff0 + kbB);
            ldsm4(b1[0], b1[1], b1[2], b1[3], sB + bOff1 + kbB);
            #pragma unroll
            for (int mt = 0; mt < 4; mt++) {
                uint32_t af[4];
                ldsm4(af[0], af[1], af[2], af[3], sA + aOff[mt] + kbB);
                #pragma unroll
                for (int nt = 0; nt < 4; nt++)
                    mma16(acc[mt][nt], af, b0[nt], b1[nt]);
            }
        }
    }

    // ---------------- epilogue ----------------
    if (MODE == 4) {
        __half* Ch = (__half*)C;
        const int wq = wid >> 1;
        #pragma unroll
        for (int mt = 0; mt < 4; mt++) {
            #pragma unroll
            for (int h = 0; h < 2; h++) {
                const int row = r0 + wm + mt * 16 + r + h * 8;
                #pragma unroll
                for (int nt = 0; nt < 2; nt++) {
                    const int ucol = c0 + wq * 16 + nt * 8 + 2 * c;
                    float2 bu = *(const float2*)(bias + ucol);
                    float2 bg = *(const float2*)(bias + DINNER + ucol);
                    float ux = acc[mt][nt][2*h+0] + bu.x;
                    float uy = acc[mt][nt][2*h+1] + bu.y;
                    float gx = acc[mt][nt+2][2*h+0] + bg.x;
                    float gy = acc[mt][nt+2][2*h+1] + bg.y;
                    float vx = ux * gx / (1.0f + __expf(-gx));
                    float vy = uy * gy / (1.0f + __expf(-gy));
                    *(__half2*)(Ch + (size_t)row * DINNER + ucol) =
                        __floats2half2_rn(vx, vy);
                }
            }
        }
        return;
    }

    #pragma unroll
    for (int mt = 0; mt < 4; mt++) {
        #pragma unroll
        for (int h = 0; h < 2; h++) {
            const int row = r0 + wm + mt * 16 + r + h * 8;
            const int s   = row & (SEQ - 1);
            float dec = 1.0f, mk = 1.0f;
            if (MODE == 2) dec = (((s + 1) % 10) == 0) ? 0.1f : 1.0f;
            if (MODE == 3) mk  = (mask[row] != 0) ? 1.0f : 0.0f;
            #pragma unroll
            for (int nt = 0; nt < 4; nt++) {
                const int col = c0 + wn + nt * 8 + 2 * c;
                float2 bv = *(const float2*)(bias + col);
                float2 v;
                v.x = acc[mt][nt][2*h+0] + bv.x;
                v.y = acc[mt][nt][2*h+1] + bv.y;
                if (MODE == 1) {
                    float2 p = *(const float2*)(aux + (size_t)s * DMODEL + col);
                    v.x += p.x; v.y += p.y;
                }
                if (MODE == 2) {
                    float2 xv = *(const float2*)(aux + (size_t)row * Nfull + col);
                    v.x = (v.x + xv.x) * dec;
                    v.y = (v.y + xv.y) * dec;
                }
                if (MODE == 3) {
                    v.x *= mk; v.y *= mk;
                    if (col < FDIM)
                        *(float2*)(C + (size_t)row * FDIM + col) = v;
                    else
                        *(float2*)(out2 + (size_t)row * VOCAB + (col - FDIM)) = v;
                } else {
                    *(float2*)(C + (size_t)row * Nfull + col) = v;
                }
            }
        }
    }
}

// ---------------- fused prep: all weight/input conversion in ONE launch ----------------
__device__ __forceinline__ void tile_transpose(
    float (*t)[33], const float* __restrict__ in, __half* __restrict__ out, int K, int N)
{
    const int n0 = blockIdx.x * 32, k0 = blockIdx.y * 32;
    const int x = threadIdx.x, y = threadIdx.y;
    #pragma unroll
    for (int i = 0; i < 32; i += 8)
        t[y + i][x] = in[(size_t)(k0 + y + i) * N + n0 + x];
    __syncthreads();
    #pragma unroll
    for (int i = 0; i < 32; i += 8)
        out[(size_t)(n0 + y + i) * K + k0 + x] = __float2half_rn(t[x][y + i]);
}

__global__ void prep_all(const float* __restrict__ W_in, const float* __restrict__ W_out,
                         const float* __restrict__ W_in_proj,
                         const float* __restrict__ Wf, const float* __restrict__ bf,
                         const float* __restrict__ Ws, const float* __restrict__ bs,
                         const float* __restrict__ frames,
                         __half* __restrict__ btI, __half* __restrict__ btO,
                         __half* __restrict__ btP,
                         __half* __restrict__ wht, float* __restrict__ bh,
                         __half* __restrict__ fr)
{
    __shared__ float t[32][33];
    const int z = blockIdx.z;
    if (z < 4) {
        if (blockIdx.y >= DMODEL / 32) return;
        tile_transpose(t, W_in + (size_t)z * DMODEL * 2 * DINNER,
                       btI + (size_t)z * 2 * DINNER * DMODEL, DMODEL, 2 * DINNER);
    } else if (z < 8) {
        if (blockIdx.x >= DMODEL / 32) return;
        tile_transpose(t, W_out + (size_t)(z - 4) * DINNER * DMODEL,
                       btO + (size_t)(z - 4) * DMODEL * DINNER, DINNER, DMODEL);
    } else if (z == 8) {
        if (blockIdx.x >= DMODEL / 32 || blockIdx.y >= FDIM / 32) return;
        tile_transpose(t, W_in_proj, btP, FDIM, DMODEL);
    } else {
        const int flat = (blockIdx.y * 64 + blockIdx.x) * 256 + threadIdx.y * 32 + threadIdx.x;
        {
            float4 v = ((const float4*)frames)[flat];
            __half2* o = (__half2*)fr + 2 * flat;
            o[0] = __floats2half2_rn(v.x, v.y);
            o[1] = __floats2half2_rn(v.z, v.w);
        }
        if (flat < DMODEL * NHEADS) {
            const int rr = flat / NHEADS, cc = flat % NHEADS;
            wht[(size_t)cc * DMODEL + rr] =
                __float2half_rn((cc < FDIM) ? Wf[rr * FDIM + cc] : Ws[rr * VOCAB + (cc - FDIM)]);
        }
        if (flat < NHEADS) bh[flat] = (flat < FDIM) ? bf[flat] : bs[flat - FDIM];
    }
}

// ---------------- LayerNorm: one warp per row; half output ----------------
__global__ __launch_bounds__(256)
void ln_kernel(const float* __restrict__ x, const float* __restrict__ sc,
               const float* __restrict__ bi, __half* __restrict__ out)
{
    const int row  = blockIdx.x * 8 + threadIdx.y;
    const int lane = threadIdx.x;
    const float4* xr = (const float4*)(x + (size_t)row * DMODEL);
    float4 v[4]; float s = 0.f;
    #pragma unroll
    for (int i = 0; i < 4; i++) { v[i] = xr[lane + 32*i]; s += v[i].x + v[i].y + v[i].z + v[i].w; }
    #pragma unroll
    for (int o = 16; o > 0; o >>= 1) s += __shfl_xor_sync(0xffffffffu, s, o);
    const float mu = s * (1.0f / DMODEL);
    float q = 0.f;
    #pragma unroll
    for (int i = 0; i < 4; i++) {
        float d;
        d = v[i].x - mu; q += d*d;  d = v[i].y - mu; q += d*d;
        d = v[i].z - mu; q += d*d;  d = v[i].w - mu; q += d*d;
    }
    #pragma unroll
    for (int o = 16; o > 0; o >>= 1) q += __shfl_xor_sync(0xffffffffu, q, o);
    const float inv = rsqrtf(q * (1.0f / DMODEL) + 1e-5f);
    const float4* s4 = (const float4*)sc;
    const float4* b4 = (const float4*)bi;
    __half2* o2 = (__half2*)(out + (size_t)row * DMODEL);
    #pragma unroll
    for (int i = 0; i < 4; i++) {
        const int cc = lane + 32*i;
        float4 sv = s4[cc], bv = b4[cc];
        float rx = (v[i].x - mu) * inv * sv.x + bv.x;
        float ry = (v[i].y - mu) * inv * sv.y + bv.y;
        float rz = (v[i].z - mu) * inv * sv.z + bv.z;
        float rw = (v[i].w - mu) * inv * sv.w + bv.w;
        o2[2*cc]   = __floats2half2_rn(rx, ry);
        o2[2*cc+1] = __floats2half2_rn(rz, rw);
    }
}

// -----------------------------------------------------------------------------
extern "C" void kernel_launch(void* const* d_in, const int* in_sizes, int n_in,
                              void* d_out, int out_size)
{
    const float* frames    = (const float*)d_in[0];
    const int*   mask      = (const int*)d_in[1];
    const float* W_in_proj = (const float*)d_in[2];
    const float* b_in_proj = (const float*)d_in[3];
    const float* pos_emb   = (const float*)d_in[4];
    const float* ln_scale  = (const float*)d_in[5];
    const float* ln_bias   = (const float*)d_in[6];
    const float* W_in      = (const float*)d_in[7];
    const float* b_in      = (const float*)d_in[8];
    const float* W_out     = (const float*)d_in[9];
    const float* b_out     = (const float*)d_in[10];
    const float* fn_scale  = (const float*)d_in[11];
    const float* fn_bias   = (const float*)d_in[12];
    const float* W_frame   = (const float*)d_in[13];
    const float* b_frame   = (const float*)d_in[14];
    const float* W_sym     = (const float*)d_in[15];
    const float* b_sym     = (const float*)d_in[16];

    float *px, *pbh;
    __half *pn, *ph, *pfr, *pbtP, *pbtI, *pbtO, *pwht;
    cudaGetSymbolAddress((void**)&px,   g_x);
    cudaGetSymbolAddress((void**)&pn,   g_n);
    cudaGetSymbolAddress((void**)&ph,   g_h);
    cudaGetSymbolAddress((void**)&pfr,  g_fr);
    cudaGetSymbolAddress((void**)&pbtP, g_bt_inproj);
    cudaGetSymbolAddress((void**)&pbtI, g_bt_win);
    cudaGetSymbolAddress((void**)&pbtO, g_bt_wout);
    cudaGetSymbolAddress((void**)&pwht, g_wh_t);
    cudaGetSymbolAddress((void**)&pbh,  g_bh);

    float* out_frame = (float*)d_out;
    float* out_sym   = (float*)d_out + (size_t)NTOK * FDIM;

    cudaFuncSetAttribute(gemm_mma<1,128>,  cudaFuncAttributeMaxDynamicSharedMemorySize, SMEM_BYTES);
    cudaFuncSetAttribute(gemm_mma<4,512>,  cudaFuncAttributeMaxDynamicSharedMemorySize, SMEM_BYTES);
    cudaFuncSetAttribute(gemm_mma<2,1024>, cudaFuncAttributeMaxDynamicSharedMemorySize, SMEM_BYTES);
    cudaFuncSetAttribute(gemm_mma<3,512>,  cudaFuncAttributeMaxDynamicSharedMemorySize, SMEM_BYTES);

    // ---- single fused prep launch ----
    {
        dim3 b(32, 8);
        dim3 g(64, 32, 10);
        prep_all<<<g, b>>>(W_in, W_out, W_in_proj, W_frame, b_frame, W_sym, b_sym,
                           frames, pbtI, pbtO, pbtP, pwht, pbh, pfr);
    }

    const dim3 lnb(32, 8);
    const int  lng = NTOK / 8;

    // 1) in_proj + pos_emb
    gemm_mma<1,128><<<dim3(DMODEL/128, NTOK/128), 256, SMEM_BYTES>>>(
        pfr, pbtP, b_in_proj, px, DMODEL, pos_emb, nullptr, nullptr);

    // 2) layers: LN -> fused GEMM+GLU -> GEMM+residual
    for (int l = 0; l < NLAYERS; l++) {
        ln_kernel<<<lng, lnb>>>(px, ln_scale + l*DMODEL, ln_bias + l*DMODEL, pn);

        gemm_mma<4,512><<<dim3(DINNER/64, NTOK/128), 256, SMEM_BYTES>>>(
            pn, pbtI + (size_t)l * 2*DINNER*DMODEL,
            b_in + (size_t)l * 2*DINNER, (float*)ph, DINNER,
            nullptr, nullptr, nullptr);

        gemm_mma<2,1024><<<dim3(DMODEL/128, NTOK/128), 256, SMEM_BYTES>>>(
            ph, pbtO + (size_t)l * DMODEL*DINNER,
            b_out + (size_t)l * DMODEL, px, DMODEL,
            px, nullptr, nullptr);
    }

    // 3) final LN
    ln_kernel<<<lng, lnb>>>(px, fn_scale, fn_bias, pn);

    // 4) heads
    gemm_mma<3,512><<<dim3(NHEADS/128, NTOK/128), 256, SMEM_BYTES>>>(
        pn, pwht, pbh, out_frame, NHEADS,
        nullptr, mask, out_sym);
}

// round 17
// speedup vs baseline: 1.3013x; 1.0183x over previous
#include <cuda_runtime.h>
#include <cuda_fp16.h>
#include <math.h>
#include <stdint.h>

#define BATCH   8
#define SEQ     2048
#define NTOK    16384
#define FDIM    128
#define DMODEL  512
#define DINNER  1024
#define NLAYERS 4
#define VOCAB   256
#define NHEADS  384

// ---------------- scratch (device globals; no allocs) ----------------
__device__ float  g_x [NTOK * DMODEL];                        // residual (fp32)
__device__ __half g_n [NTOK * DMODEL];                        // LN out
__device__ __half g_h [NTOK * DINNER];                        // GLU out
__device__ __half g_fr[NTOK * FDIM];                          // frames
__device__ __half g_bt_inproj[DMODEL * FDIM];
__device__ __half g_bt_win   [NLAYERS * 2 * DINNER * DMODEL];
__device__ __half g_bt_wout  [NLAYERS * DMODEL * DINNER];
__device__ __half g_wh_t     [NHEADS * DMODEL];
__device__ float  g_bh       [NHEADS];

// ---------------- helpers ----------------
__device__ __forceinline__ uint32_t smem_u32(const void* p) {
    uint32_t a;
    asm("{ .reg .u64 t; cvta.to.shared.u64 t, %1; cvt.u32.u64 %0, t; }" : "=r"(a) : "l"(p));
    return a;
}
__device__ __forceinline__ void mma16(float* d, const uint32_t* a, uint32_t b0, uint32_t b1) {
    asm volatile("mma.sync.aligned.m16n8k16.row.col.f32.f16.f16.f32 "
                 "{%0,%1,%2,%3}, {%4,%5,%6,%7}, {%8,%9}, {%0,%1,%2,%3};"
                 : "+f"(d[0]), "+f"(d[1]), "+f"(d[2]), "+f"(d[3])
                 : "r"(a[0]), "r"(a[1]), "r"(a[2]), "r"(a[3]), "r"(b0), "r"(b1));
}
__device__ __forceinline__ void ldsm4(uint32_t& r0, uint32_t& r1, uint32_t& r2, uint32_t& r3,
                                      uint32_t addr) {
    asm volatile("ldmatrix.sync.aligned.m8n8.x4.shared.b16 {%0,%1,%2,%3}, [%4];"
                 : "=r"(r0), "=r"(r1), "=r"(r2), "=r"(r3) : "r"(addr));
}
__device__ __forceinline__ void cpa16(uint32_t s, const void* g) {
    asm volatile("cp.async.cg.shared.global [%0], [%1], 16;" :: "r"(s), "l"(g));
}
#define CP_COMMIT() asm volatile("cp.async.commit_group;")
#define CP_WAIT1()  asm volatile("cp.async.wait_group 1;")
#define CP_WAIT0()  asm volatile("cp.async.wait_group 0;")

#define CHK    64
#define LDKB   144                     // row stride bytes: aligned + LDSM conflict-free
#define TILE_A (128 * LDKB)            // 18432 B (A: 128 rows)
#define TILE_BS (64 * LDKB)            // 9216 B  (B: 64 rows)
#define STAGE_B (TILE_A + TILE_BS)     // 27648 B
#define NSTAGE 2
#define SMEM_BYTES (NSTAGE * STAGE_B)  // 55296 -> 3 CTAs/SM (24 warps)

// ---- fp16 mma.sync GEMM (fp32 accum): CTA 128x64, warp 32x32, 3 CTAs/SM ----
// MODE 1: C = acc + bias + pos_emb[s,col]          (fp32 out)
// MODE 2: C = (aux + acc + bias) * decay(s)        (fp32 out, in-place residual)
// MODE 3: heads: mask ? acc+bias : 0; split frame/sym (fp32 out)
// MODE 4: GLU fused (CTA covers 32 u + 32 g cols): h = u*silu(g), half out
template<int MODE, int KT>
__global__ __launch_bounds__(256, 3)
void gemm_mma(const __half* __restrict__ A, const __half* __restrict__ Bt,
              const float* __restrict__ bias, float* __restrict__ C,
              int Nfull,
              const float* __restrict__ aux, const int* __restrict__ mask,
              float* __restrict__ out2)
{
    extern __shared__ uint32_t smem[];
    const int tid  = threadIdx.x;
    const int wid  = tid >> 5, lane = tid & 31;
    const int r    = lane >> 2, c = lane & 3;
    const int wm   = (wid & 3) * 32;      // 4x2 warps: warp tile 32x32
    const int wn   = (wid >> 2) * 32;
    const int r0   = blockIdx.y * 128;
    const int c0   = blockIdx.x * ((MODE == 4) ? 32 : 64);

    const int srw = tid >> 3;             // 0..31
    const int seg = (tid & 7) * 16;       // byte offset in row

    auto browf = [&](int t) -> int {      // staged B row (0..63) -> global Bt row
        if (MODE == 4) {
            const int wq = t >> 5, i5 = t & 31;
            return c0 + wq * 16 + (i5 & 15) + ((i5 >> 4) ? DINNER : 0);
        }
        return c0 + t;
    };

    const uint32_t sbase = smem_u32(smem);
    constexpr int nch = KT / CHK;

    auto stage = [&](int ch, int buf) {
        const int kc = ch * CHK;
        const uint32_t aB = sbase + buf * STAGE_B;
        const uint32_t bB = aB + TILE_A;
        #pragma unroll
        for (int i = 0; i < 4; i++) {     // A: 128 rows
            const int rw = srw + 32 * i;
            cpa16(aB + rw * LDKB + seg,
                  A + (size_t)(r0 + rw) * KT + kc + seg / 2);
        }
        #pragma unroll
        for (int i = 0; i < 2; i++) {     // B: 64 rows
            const int rw = srw + 32 * i;
            cpa16(bB + rw * LDKB + seg,
                  Bt + (size_t)browf(rw) * KT + kc + seg / 2);
        }
        CP_COMMIT();
    };

    // ldmatrix per-lane byte offsets (within a staged tile)
    const int aRow = (lane & 7) + ((lane >> 3) & 1) * 8;
    const int aKh  = lane >> 4;
    uint32_t aOff[2];
    #pragma unroll
    for (int mt = 0; mt < 2; mt++)
        aOff[mt] = (wm + mt * 16 + aRow) * LDKB + aKh * 16;
    const int bN = wn + (lane >> 3) * 8 + (lane & 7);
    const uint32_t bOff0 = bN * LDKB;     // kh0: nt tiles 0..3
    const uint32_t bOff1 = bN * LDKB + 16;// kh1

    float acc[2][4][4];
    #pragma unroll
    for (int mt = 0; mt < 2; mt++)
        #pragma unroll
        for (int nt = 0; nt < 4; nt++)
            #pragma unroll
            for (int q = 0; q < 4; q++) acc[mt][nt][q] = 0.f;

    stage(0, 0);
    if (nch > 1) stage(1, 1);

    #pragma unroll
    for (int ch = 0; ch < nch; ch++) {
        const int buf = ch & 1;
        if (ch + 1 < nch) { CP_WAIT1(); } else { CP_WAIT0(); }
        __syncthreads();

        const uint32_t sA = sbase + buf * STAGE_B;
        const uint32_t sB = sA + TILE_A;
        #pragma unroll
        for (int ks = 0; ks < 4; ks++) {
            const uint32_t kbB = ks * 32;
            uint32_t b0[4], b1[4];
            ldsm4(b0[0], b0[1], b0[2], b0[3], sB + bOff0 + kbB);
            ldsm4(b1[0], b1[1], b1[2], b1[3], sB + bOff1 + kbB);
            #pragma unroll
            for (int mt = 0; mt < 2; mt++) {
                uint32_t af[4];
                ldsm4(af[0], af[1], af[2], af[3], sA + aOff[mt] + kbB);
                #pragma unroll
                for (int nt = 0; nt < 4; nt++)
                    mma16(acc[mt][nt], af, b0[nt], b1[nt]);
            }
        }
        __syncthreads();
        if (ch + 2 < nch) stage(ch + 2, buf);
    }

    // ---------------- epilogue ----------------
    if (MODE == 4) {
        __half* Ch = (__half*)C;
        const int wq = wn >> 5;           // 0 or 1
        #pragma unroll
        for (int mt = 0; mt < 2; mt++) {
            #pragma unroll
            for (int h = 0; h < 2; h++) {
                const int row = r0 + wm + mt * 16 + r + h * 8;
                #pragma unroll
                for (int nt = 0; nt < 2; nt++) {
                    const int ucol = c0 + wq * 16 + nt * 8 + 2 * c;
                    float2 bu = *(const float2*)(bias + ucol);
                    float2 bg = *(const float2*)(bias + DINNER + ucol);
                    float ux = acc[mt][nt][2*h+0] + bu.x;
                    float uy = acc[mt][nt][2*h+1] + bu.y;
                    float gx = acc[mt][nt+2][2*h+0] + bg.x;
                    float gy = acc[mt][nt+2][2*h+1] + bg.y;
                    float vx = ux * gx / (1.0f + __expf(-gx));
                    float vy = uy * gy / (1.0f + __expf(-gy));
                    *(__half2*)(Ch + (size_t)row * DINNER + ucol) =
                        __floats2half2_rn(vx, vy);
                }
            }
        }
        return;
    }

    #pragma unroll
    for (int mt = 0; mt < 2; mt++) {
        #pragma unroll
        for (int h = 0; h < 2; h++) {
            const int row = r0 + wm + mt * 16 + r + h * 8;
            const int s   = row & (SEQ - 1);
            float dec = 1.0f, mk = 1.0f;
            if (MODE == 2) dec = (((s + 1) % 10) == 0) ? 0.1f : 1.0f;
            if (MODE == 3) mk  = (mask[row] != 0) ? 1.0f : 0.0f;
            #pragma unroll
            for (int nt = 0; nt < 4; nt++) {
                const int col = c0 + wn + nt * 8 + 2 * c;
                float2 bv = *(const float2*)(bias + col);
                float2 v;
                v.x = acc[mt][nt][2*h+0] + bv.x;
                v.y = acc[mt][nt][2*h+1] + bv.y;
                if (MODE == 1) {
                    float2 p = *(const float2*)(aux + (size_t)s * DMODEL + col);
                    v.x += p.x; v.y += p.y;
                }
                if (MODE == 2) {
                    float2 xv = *(const float2*)(aux + (size_t)row * Nfull + col);
                    v.x = (v.x + xv.x) * dec;
                    v.y = (v.y + xv.y) * dec;
                }
                if (MODE == 3) {
                    v.x *= mk; v.y *= mk;
                    if (col < FDIM)
                        *(float2*)(C + (size_t)row * FDIM + col) = v;
                    else
                        *(float2*)(out2 + (size_t)row * VOCAB + (col - FDIM)) = v;
                } else {
                    *(float2*)(C + (size_t)row * Nfull + col) = v;
                }
            }
        }
    }
}

// ---------------- fused prep: all weight/input conversion in ONE launch ----------------
__device__ __forceinline__ void tile_transpose(
    float (*t)[33], const float* __restrict__ in, __half* __restrict__ out, int K, int N)
{
    const int n0 = blockIdx.x * 32, k0 = blockIdx.y * 32;
    const int x = threadIdx.x, y = threadIdx.y;
    #pragma unroll
    for (int i = 0; i < 32; i += 8)
        t[y + i][x] = in[(size_t)(k0 + y + i) * N + n0 + x];
    __syncthreads();
    #pragma unroll
    for (int i = 0; i < 32; i += 8)
        out[(size_t)(n0 + y + i) * K + k0 + x] = __float2half_rn(t[x][y + i]);
}

__global__ void prep_all(const float* __restrict__ W_in, const float* __restrict__ W_out,
                         const float* __restrict__ W_in_proj,
                         const float* __restrict__ Wf, const float* __restrict__ bf,
                         const float* __restrict__ Ws, const float* __restrict__ bs,
                         const float* __restrict__ frames,
                         __half* __restrict__ btI, __half* __restrict__ btO,
                         __half* __restrict__ btP,
                         __half* __restrict__ wht, float* __restrict__ bh,
                         __half* __restrict__ fr)
{
    __shared__ float t[32][33];
    const int z = blockIdx.z;
    if (z < 4) {
        if (blockIdx.y >= DMODEL / 32) return;
        tile_transpose(t, W_in + (size_t)z * DMODEL * 2 * DINNER,
                       btI + (size_t)z * 2 * DINNER * DMODEL, DMODEL, 2 * DINNER);
    } else if (z < 8) {
        if (blockIdx.x >= DMODEL / 32) return;
        tile_transpose(t, W_out + (size_t)(z - 4) * DINNER * DMODEL,
                       btO + (size_t)(z - 4) * DMODEL * DINNER, DINNER, DMODEL);
    } else if (z == 8) {
        if (blockIdx.x >= DMODEL / 32 || blockIdx.y >= FDIM / 32) return;
        tile_transpose(t, W_in_proj, btP, FDIM, DMODEL);
    } else {
        const int flat = (blockIdx.y * 64 + blockIdx.x) * 256 + threadIdx.y * 32 + threadIdx.x;
        {
            float4 v = ((const float4*)frames)[flat];
            __half2* o = (__half2*)fr + 2 * flat;
            o[0] = __floats2half2_rn(v.x, v.y);
            o[1] = __floats2half2_rn(v.z, v.w);
        }
        if (flat < DMODEL * NHEADS) {
            const int rr = flat / NHEADS, cc = flat % NHEADS;
            wht[(size_t)cc * DMODEL + rr] =
                __float2half_rn((cc < FDIM) ? Wf[rr * FDIM + cc] : Ws[rr * VOCAB + (cc - FDIM)]);
        }
        if (flat < NHEADS) bh[flat] = (flat < FDIM) ? bf[flat] : bs[flat - FDIM];
    }
}

// ---------------- LayerNorm: one warp per row; half output ----------------
__global__ __launch_bounds__(256)
void ln_kernel(const float* __restrict__ x, const float* __restrict__ sc,
               const float* __restrict__ bi, __half* __restrict__ out)
{
    const int row  = blockIdx.x * 8 + threadIdx.y;
    const int lane = threadIdx.x;
    const float4* xr = (const float4*)(x + (size_t)row * DMODEL);
    float4 v[4]; float s = 0.f;
    #pragma unroll
    for (int i = 0; i < 4; i++) { v[i] = xr[lane + 32*i]; s += v[i].x + v[i].y + v[i].z + v[i].w; }
    #pragma unroll
    for (int o = 16; o > 0; o >>= 1) s += __shfl_xor_sync(0xffffffffu, s, o);
    const float mu = s * (1.0f / DMODEL);
    float q = 0.f;
    #pragma unroll
    for (int i = 0; i < 4; i++) {
        float d;
        d = v[i].x - mu; q += d*d;  d = v[i].y - mu; q += d*d;
        d = v[i].z - mu; q += d*d;  d = v[i].w - mu; q += d*d;
    }
    #pragma unroll
    for (int o = 16; o > 0; o >>= 1) q += __shfl_xor_sync(0xffffffffu, q, o);
    const float inv = rsqrtf(q * (1.0f / DMODEL) + 1e-5f);
    const float4* s4 = (const float4*)sc;
    const float4* b4 = (const float4*)bi;
    __half2* o2 = (__half2*)(out + (size_t)row * DMODEL);
    #pragma unroll
    for (int i = 0; i < 4; i++) {
        const int cc = lane + 32*i;
        float4 sv = s4[cc], bv = b4[cc];
        float rx = (v[i].x - mu) * inv * sv.x + bv.x;
        float ry = (v[i].y - mu) * inv * sv.y + bv.y;
        float rz = (v[i].z - mu) * inv * sv.z + bv.z;
        float rw = (v[i].w - mu) * inv * sv.w + bv.w;
        o2[2*cc]   = __floats2half2_rn(rx, ry);
        o2[2*cc+1] = __floats2half2_rn(rz, rw);
    }
}

// -----------------------------------------------------------------------------
extern "C" void kernel_launch(void* const* d_in, const int* in_sizes, int n_in,
                              void* d_out, int out_size)
{
    const float* frames    = (const float*)d_in[0];
    const int*   mask      = (const int*)d_in[1];
    const float* W_in_proj = (const float*)d_in[2];
    const float* b_in_proj = (const float*)d_in[3];
    const float* pos_emb   = (const float*)d_in[4];
    const float* ln_scale  = (const float*)d_in[5];
    const float* ln_bias   = (const float*)d_in[6];
    const float* W_in      = (const float*)d_in[7];
    const float* b_in      = (const float*)d_in[8];
    const float* W_out     = (const float*)d_in[9];
    const float* b_out     = (const float*)d_in[10];
    const float* fn_scale  = (const float*)d_in[11];
    const float* fn_bias   = (const float*)d_in[12];
    const float* W_frame   = (const float*)d_in[13];
    const float* b_frame   = (const float*)d_in[14];
    const float* W_sym     = (const float*)d_in[15];
    const float* b_sym     = (const float*)d_in[16];

    float *px, *pbh;
    __half *pn, *ph, *pfr, *pbtP, *pbtI, *pbtO, *pwht;
    cudaGetSymbolAddress((void**)&px,   g_x);
    cudaGetSymbolAddress((void**)&pn,   g_n);
    cudaGetSymbolAddress((void**)&ph,   g_h);
    cudaGetSymbolAddress((void**)&pfr,  g_fr);
    cudaGetSymbolAddress((void**)&pbtP, g_bt_inproj);
    cudaGetSymbolAddress((void**)&pbtI, g_bt_win);
    cudaGetSymbolAddress((void**)&pbtO, g_bt_wout);
    cudaGetSymbolAddress((void**)&pwht, g_wh_t);
    cudaGetSymbolAddress((void**)&pbh,  g_bh);

    float* out_frame = (float*)d_out;
    float* out_sym   = (float*)d_out + (size_t)NTOK * FDIM;

    cudaFuncSetAttribute(gemm_mma<1,128>,  cudaFuncAttributeMaxDynamicSharedMemorySize, SMEM_BYTES);
    cudaFuncSetAttribute(gemm_mma<4,512>,  cudaFuncAttributeMaxDynamicSharedMemorySize, SMEM_BYTES);
    cudaFuncSetAttribute(gemm_mma<2,1024>, cudaFuncAttributeMaxDynamicSharedMemorySize, SMEM_BYTES);
    cudaFuncSetAttribute(gemm_mma<3,512>,  cudaFuncAttributeMaxDynamicSharedMemorySize, SMEM_BYTES);

    // ---- single fused prep launch ----
    {
        dim3 b(32, 8);
        dim3 g(64, 32, 10);
        prep_all<<<g, b>>>(W_in, W_out, W_in_proj, W_frame, b_frame, W_sym, b_sym,
                           frames, pbtI, pbtO, pbtP, pwht, pbh, pfr);
    }

    const dim3 lnb(32, 8);
    const int  lng = NTOK / 8;

    // 1) in_proj + pos_emb
    gemm_mma<1,128><<<dim3(DMODEL/64, NTOK/128), 256, SMEM_BYTES>>>(
        pfr, pbtP, b_in_proj, px, DMODEL, pos_emb, nullptr, nullptr);

    // 2) layers: LN -> fused GEMM+GLU -> GEMM+residual
    for (int l = 0; l < NLAYERS; l++) {
        ln_kernel<<<lng, lnb>>>(px, ln_scale + l*DMODEL, ln_bias + l*DMODEL, pn);

        gemm_mma<4,512><<<dim3(DINNER/32, NTOK/128), 256, SMEM_BYTES>>>(
            pn, pbtI + (size_t)l * 2*DINNER*DMODEL,
            b_in + (size_t)l * 2*DINNER, (float*)ph, DINNER,
            nullptr, nullptr, nullptr);

        gemm_mma<2,1024><<<dim3(DMODEL/64, NTOK/128), 256, SMEM_BYTES>>>(
            ph, pbtO + (size_t)l * DMODEL*DINNER,
            b_out + (size_t)l * DMODEL, px, DMODEL,
            px, nullptr, nullptr);
    }

    // 3) final LN
    ln_kernel<<<lng, lnb>>>(px, fn_scale, fn_bias, pn);

    // 4) heads
    gemm_mma<3,512><<<dim3(NHEADS/64, NTOK/128), 256, SMEM_BYTES>>>(
        pn, pwht, pbh, out_frame, NHEADS,
        nullptr, mask, out_sym);
}